// round 4
// baseline (speedup 1.0000x reference)
#include <cuda_runtime.h>
#include <math.h>

// ---------------- problem constants ----------------
#define PB 2
#define PN 384
#define PK 384
#define PCZ 128
#define PCOUT 128
#define PBINS 16
#define PCIN (PCZ + PBINS)   // 144

#define F_EPS 1e-8f
#define F_LNEPS 1e-5f
#define F_DMAX 10.0f

// output layout: [Z_c | Z_sem_c | Z_geo_c]
#define SZ_ZC   ((long long)PB * PK * PK * PCOUT)      // 37748736
#define OFF_SEM (SZ_ZC)
#define SZ_SEM  ((long long)PB * PK * PN * PCZ)        // 37748736
#define OFF_GEO (OFF_SEM + SZ_SEM)                     // 75497472

// scratch reductions
__device__ float g_s[PB * PN];    // s[b,n] = mf[b,n] * sum_k A[b,n,k]
__device__ float g_col[PB * PK];  // col[b,a] = sum_n A[b,n,a]*mf[b,n]

// ---------------- K0: row/col reductions ----------------
__global__ void reduce_kernel(const float* __restrict__ A,
                              const float* __restrict__ mask_f) {
    int b = blockIdx.x;
    int t = threadIdx.x;  // 0..383
    if (blockIdx.y == 0) {
        const float* row = A + ((long long)b * PN + t) * PK;
        float s = 0.f;
        for (int k = 0; k < PK; ++k) s += row[k];
        g_s[b * PN + t] = s * mask_f[b * PN + t];
    } else {
        float s = 0.f;
        for (int n = 0; n < PN; ++n)
            s += A[((long long)b * PN + n) * PK + t] * mask_f[b * PN + n];
        g_col[b * PK + t] = s;
    }
}

// ---------------- K1: semantic-coarsening GEMM + epilogue ----------------
// C[a, m*128+z] = sum_n (A[b,n,a]*mf[n]^2) * Z[b,n,m,z]
// Z_sem[b,a,m,z] = C * mf[m]*s[m] / max(col[a]*s[m], EPS)
// grid: (m=384, aBlk=3, b=2); 256 threads; BM=BN=128, BK=16, 8x8/thread
__global__ __launch_bounds__(256, 2) void sem_gemm(
    const float* __restrict__ A, const float* __restrict__ Z,
    const float* __restrict__ mask_f, float* __restrict__ out) {
    __shared__ float sA[16 * 132];
    __shared__ float sB[16 * 128];

    const int m    = blockIdx.x;   // fine-residue index (= column block, since CZ==128)
    const int aBlk = blockIdx.y;
    const int b    = blockIdx.z;
    const int tid  = threadIdx.x;
    const int tx   = tid & 15, ty = tid >> 4;

    const float* Ab  = A + (long long)b * PN * PK + aBlk * 128;
    const float* Zb  = Z + (long long)b * PN * PN * PCZ + (long long)m * PCZ;
    const float* mfb = mask_f + b * PN;

    float acc[8][8];
#pragma unroll
    for (int i = 0; i < 8; ++i)
#pragma unroll
        for (int j = 0; j < 8; ++j) acc[i][j] = 0.f;

    for (int k0 = 0; k0 < PK; k0 += 16) {
        // A tile: row k=ty, cols a = tx*8..+7 ; fold mf^2
        {
            float mf  = mfb[k0 + ty];
            float mf2 = mf * mf;
            const float* p = Ab + (long long)(k0 + ty) * PK + tx * 8;
            float4 v0 = *(const float4*)p;
            float4 v1 = *(const float4*)(p + 4);
            v0.x *= mf2; v0.y *= mf2; v0.z *= mf2; v0.w *= mf2;
            v1.x *= mf2; v1.y *= mf2; v1.z *= mf2; v1.w *= mf2;
            float* d = &sA[ty * 132 + tx * 8];
            *(float4*)d = v0; *(float4*)(d + 4) = v1;
        }
        // B tile: row k=ty, cols z = tx*8..+7
        {
            const float* p = Zb + (long long)(k0 + ty) * (PN * PCZ) + tx * 8;
            float4 v0 = *(const float4*)p;
            float4 v1 = *(const float4*)(p + 4);
            float* d = &sB[ty * 128 + tx * 8];
            *(float4*)d = v0; *(float4*)(d + 4) = v1;
        }
        __syncthreads();
#pragma unroll
        for (int kt = 0; kt < 16; ++kt) {
            float4 a0 = *(const float4*)&sA[kt * 132 + ty * 8];
            float4 a1 = *(const float4*)&sA[kt * 132 + ty * 8 + 4];
            float4 b0 = *(const float4*)&sB[kt * 128 + tx * 8];
            float4 b1 = *(const float4*)&sB[kt * 128 + tx * 8 + 4];
            float af[8] = {a0.x, a0.y, a0.z, a0.w, a1.x, a1.y, a1.z, a1.w};
            float bf[8] = {b0.x, b0.y, b0.z, b0.w, b1.x, b1.y, b1.z, b1.w};
#pragma unroll
            for (int i = 0; i < 8; ++i)
#pragma unroll
                for (int j = 0; j < 8; ++j) acc[i][j] = fmaf(af[i], bf[j], acc[i][j]);
        }
        __syncthreads();
    }

    // epilogue
    float sm  = g_s[b * PN + m];
    float num = mfb[m] * sm;
#pragma unroll
    for (int i = 0; i < 8; ++i) {
        int a = aBlk * 128 + ty * 8 + i;
        float f = num / fmaxf(g_col[b * PK + a] * sm, F_EPS);
        float* dst = out + OFF_SEM + (((long long)b * PK + a) * PN + m) * PCZ + tx * 8;
        float4 o0, o1;
        o0.x = acc[i][0] * f; o0.y = acc[i][1] * f; o0.z = acc[i][2] * f; o0.w = acc[i][3] * f;
        o1.x = acc[i][4] * f; o1.y = acc[i][5] * f; o1.z = acc[i][6] * f; o1.w = acc[i][7] * f;
        *(float4*)dst = o0; *(float4*)(dst + 4) = o1;
    }
}

// ---------------- K2: geometry RBF ----------------
__global__ void geo_kernel(const float* __restrict__ mu,
                           const float* __restrict__ mask_c,
                           float* __restrict__ out) {
    int idx = blockIdx.x * 256 + threadIdx.x;
    if (idx >= PB * PK * PK) return;
    int b = idx / (PK * PK);
    int r = idx - b * PK * PK;
    int i = r / PK, j = r - i * PK;
    const float* mi = mu + ((long long)b * PK + i) * 3;
    const float* mj = mu + ((long long)b * PK + j) * 3;
    float dx = mi[0] - mj[0], dy = mi[1] - mj[1], dz = mi[2] - mj[2];
    float d = sqrtf(dx * dx + dy * dy + dz * dz + F_EPS);
    float mc2 = mask_c[b * PK + i] * mask_c[b * PK + j];
    const float width = F_DMAX / (PBINS - 1);
    const float invw  = (PBINS - 1) / F_DMAX;
    float* dst = out + OFF_GEO + (long long)idx * PBINS;
#pragma unroll
    for (int t = 0; t < PBINS; t += 4) {
        float4 v;
        float u;
        u = (d - (t + 0) * width) * invw; v.x = __expf(-0.5f * u * u) * mc2;
        u = (d - (t + 1) * width) * invw; v.y = __expf(-0.5f * u * u) * mc2;
        u = (d - (t + 2) * width) * invw; v.z = __expf(-0.5f * u * u) * mc2;
        u = (d - (t + 3) * width) * invw; v.w = __expf(-0.5f * u * u) * mc2;
        *(float4*)(dst + t) = v;
    }
}

// ---------------- K3: fused MLP: Linear->LN->SiLU->Linear (+mask) ----------------
// One block = 128 rows x all 128 cols. h lives in shared (sG).
// sG row stride MUST be a multiple of 4 floats (float4 staging) -> 132.
#define SG_STRIDE 132
#define SMEM_MLP_FLOATS (16 * 132 + 16 * 128 + 128 * SG_STRIDE)
__global__ __launch_bounds__(256, 2) void mlp_kernel(
    float* __restrict__ out,
    const float* __restrict__ W1, const float* __restrict__ b1,
    const float* __restrict__ lng, const float* __restrict__ lnb,
    const float* __restrict__ W2, const float* __restrict__ b2,
    const float* __restrict__ mask_c) {
    extern __shared__ float smem[];
    float* sA = smem;                       // 16 x 132, X tile (transposed: [k][r])
    float* sB = smem + 16 * 132;            // 16 x 128, weight tile
    float* sG = smem + 16 * 132 + 16 * 128; // 128 x SG_STRIDE, h / silu rows

    const int row0 = blockIdx.x * 128;
    const int tid  = threadIdx.x;
    const int tx   = tid & 15, ty = tid >> 4;
    const float* sem = out + OFF_SEM;
    const float* geo = out + OFF_GEO;

    float acc[8][8];
#pragma unroll
    for (int i = 0; i < 8; ++i)
#pragma unroll
        for (int j = 0; j < 8; ++j) acc[i][j] = 0.f;

    // ---- GEMM1: X[128 x 144] @ W1[144 x 128] ----
    for (int k0 = 0; k0 < PCIN; k0 += 16) {
        {
            int r  = tid >> 1;
            int kk = (tid & 1) * 8;
            float4 v0, v1;
            if (k0 < PCZ) {
                const float* p = sem + (long long)(row0 + r) * PCZ + k0 + kk;
                v0 = *(const float4*)p; v1 = *(const float4*)(p + 4);
            } else {
                const float* p = geo + (long long)(row0 + r) * PBINS + kk;
                v0 = *(const float4*)p; v1 = *(const float4*)(p + 4);
            }
            sA[(kk + 0) * 132 + r] = v0.x;
            sA[(kk + 1) * 132 + r] = v0.y;
            sA[(kk + 2) * 132 + r] = v0.z;
            sA[(kk + 3) * 132 + r] = v0.w;
            sA[(kk + 4) * 132 + r] = v1.x;
            sA[(kk + 5) * 132 + r] = v1.y;
            sA[(kk + 6) * 132 + r] = v1.z;
            sA[(kk + 7) * 132 + r] = v1.w;
        }
        {
            const float* p = W1 + (long long)(k0 + ty) * PCOUT + tx * 8;
            *(float4*)&sB[ty * 128 + tx * 8]     = *(const float4*)p;
            *(float4*)&sB[ty * 128 + tx * 8 + 4] = *(const float4*)(p + 4);
        }
        __syncthreads();
#pragma unroll
        for (int kt = 0; kt < 16; ++kt) {
            float4 a0 = *(const float4*)&sA[kt * 132 + ty * 8];
            float4 a1 = *(const float4*)&sA[kt * 132 + ty * 8 + 4];
            float4 b0 = *(const float4*)&sB[kt * 128 + tx * 8];
            float4 b1 = *(const float4*)&sB[kt * 128 + tx * 8 + 4];
            float af[8] = {a0.x, a0.y, a0.z, a0.w, a1.x, a1.y, a1.z, a1.w};
            float bf[8] = {b0.x, b0.y, b0.z, b0.w, b1.x, b1.y, b1.z, b1.w};
#pragma unroll
            for (int i = 0; i < 8; ++i)
#pragma unroll
                for (int j = 0; j < 8; ++j) acc[i][j] = fmaf(af[i], bf[j], acc[i][j]);
        }
        __syncthreads();
    }

    // bias + stage h rows into sG (float4 stores: SG_STRIDE is a multiple of 4)
    {
        float bv[8];
#pragma unroll
        for (int j = 0; j < 8; ++j) bv[j] = b1[tx * 8 + j];
#pragma unroll
        for (int i = 0; i < 8; ++i) {
            float* d = &sG[(ty * 8 + i) * SG_STRIDE + tx * 8];
            float4 o0, o1;
            o0.x = acc[i][0] + bv[0]; o0.y = acc[i][1] + bv[1];
            o0.z = acc[i][2] + bv[2]; o0.w = acc[i][3] + bv[3];
            o1.x = acc[i][4] + bv[4]; o1.y = acc[i][5] + bv[5];
            o1.z = acc[i][6] + bv[6]; o1.w = acc[i][7] + bv[7];
            *(float4*)d = o0; *(float4*)(d + 4) = o1;
        }
    }
    __syncthreads();

    // ---- LayerNorm + SiLU, one thread per row ----
    if (tid < 128) {
        float* g = &sG[tid * SG_STRIDE];
        float s = 0.f;
#pragma unroll 8
        for (int c = 0; c < 128; ++c) s += g[c];
        float mu = s * (1.f / 128.f);
        float vs = 0.f;
#pragma unroll 8
        for (int c = 0; c < 128; ++c) { float dd = g[c] - mu; vs = fmaf(dd, dd, vs); }
        float rstd = rsqrtf(vs * (1.f / 128.f) + F_LNEPS);
#pragma unroll 8
        for (int c = 0; c < 128; ++c) {
            float x = (g[c] - mu) * rstd * lng[c] + lnb[c];
            g[c] = x / (1.f + __expf(-x));
        }
    }

    // ---- GEMM2: silu(h)[128 x 128] @ W2[128 x 128] ----
    float acc2[8][8];
#pragma unroll
    for (int i = 0; i < 8; ++i)
#pragma unroll
        for (int j = 0; j < 8; ++j) acc2[i][j] = 0.f;

    for (int k0 = 0; k0 < PCOUT; k0 += 16) {
        __syncthreads();
        {
            const float* p = W2 + (long long)(k0 + ty) * PCOUT + tx * 8;
            *(float4*)&sB[ty * 128 + tx * 8]     = *(const float4*)p;
            *(float4*)&sB[ty * 128 + tx * 8 + 4] = *(const float4*)(p + 4);
        }
        __syncthreads();
#pragma unroll
        for (int kt = 0; kt < 16; ++kt) {
            float4 b0 = *(const float4*)&sB[kt * 128 + tx * 8];
            float4 b1 = *(const float4*)&sB[kt * 128 + tx * 8 + 4];
            float bf[8] = {b0.x, b0.y, b0.z, b0.w, b1.x, b1.y, b1.z, b1.w};
            float af[8];
#pragma unroll
            for (int i = 0; i < 8; ++i) af[i] = sG[(ty * 8 + i) * SG_STRIDE + k0 + kt];
#pragma unroll
            for (int i = 0; i < 8; ++i)
#pragma unroll
                for (int j = 0; j < 8; ++j) acc2[i][j] = fmaf(af[i], bf[j], acc2[i][j]);
        }
    }

    // ---- epilogue: +b2, *mc2, write Z_c ----
    float b2v[8];
#pragma unroll
    for (int j = 0; j < 8; ++j) b2v[j] = b2[tx * 8 + j];
#pragma unroll
    for (int i = 0; i < 8; ++i) {
        int r  = row0 + ty * 8 + i;
        int bb = r / (PK * PK);
        int rr = r - bb * PK * PK;
        int ii = rr / PK;
        int jj = rr - ii * PK;
        float mc2 = mask_c[bb * PK + ii] * mask_c[bb * PK + jj];
        float* dst = out + (long long)r * PCOUT + tx * 8;
        float4 o0, o1;
        o0.x = (acc2[i][0] + b2v[0]) * mc2; o0.y = (acc2[i][1] + b2v[1]) * mc2;
        o0.z = (acc2[i][2] + b2v[2]) * mc2; o0.w = (acc2[i][3] + b2v[3]) * mc2;
        o1.x = (acc2[i][4] + b2v[4]) * mc2; o1.y = (acc2[i][5] + b2v[5]) * mc2;
        o1.z = (acc2[i][6] + b2v[6]) * mc2; o1.w = (acc2[i][7] + b2v[7]) * mc2;
        *(float4*)dst = o0; *(float4*)(dst + 4) = o1;
    }
}

// ---------------- launch ----------------
extern "C" void kernel_launch(void* const* d_in, const int* in_sizes, int n_in,
                              void* d_out, int out_size) {
    const float* A      = (const float*)d_in[0];
    const float* Zf     = (const float*)d_in[1];
    const float* mu     = (const float*)d_in[2];
    const float* mask_f = (const float*)d_in[3];
    const float* mask_c = (const float*)d_in[4];
    const float* W1     = (const float*)d_in[5];
    const float* b1     = (const float*)d_in[6];
    const float* lng    = (const float*)d_in[7];
    const float* lnb    = (const float*)d_in[8];
    const float* W2     = (const float*)d_in[9];
    const float* b2     = (const float*)d_in[10];
    float* out = (float*)d_out;

    const int smem_mlp = SMEM_MLP_FLOATS * (int)sizeof(float);
    cudaFuncSetAttribute(mlp_kernel, cudaFuncAttributeMaxDynamicSharedMemorySize, smem_mlp);

    reduce_kernel<<<dim3(PB, 2), PK>>>(A, mask_f);
    sem_gemm<<<dim3(PN, 3, PB), 256>>>(A, Zf, mask_f, out);
    geo_kernel<<<(PB * PK * PK + 255) / 256, 256>>>(mu, mask_c, out);
    mlp_kernel<<<PB * PK * PK / 128, 256, smem_mlp>>>(out, W1, b1, lng, lnb, W2, b2, mask_c);
}